// round 3
// baseline (speedup 1.0000x reference)
#include <cuda_runtime.h>
#include <math_constants.h>

#define B_   8
#define N_   1024
#define C_   512
#define H_   8
#define D_   64
#define TOPK 16
#define M_   (B_ * N_)          // 8192 rows
#define KV_C (2 * C_)           // 1024

// Scratch (device globals; no allocation allowed)
__device__ float g_q[M_ * C_];          // relu(x@Wq+bq)
__device__ float g_kv[M_ * KV_C];       // x@Wkv+bkv  (k at col [0,512), v at [512,1024))
__device__ float g_att[M_ * C_];        // attention output (pre-projection)
__device__ float g_vsum[B_ * H_ * D_];  // per-(b,h) column sums of v

// ---------------------------------------------------------------------------
// Tiled fp32 GEMM: C = act(A[M,K] @ W[K,Nc] + bias), 128x128 tile, BK=8,
// 256 threads, 8x8 microtile per thread. M, Nc, K all multiples of tile dims.
// ---------------------------------------------------------------------------
template <bool RELU>
__global__ __launch_bounds__(256) void gemm_kernel(
    const float* __restrict__ A, const float* __restrict__ W,
    const float* __restrict__ bias, float* __restrict__ Cc, int K, int Nc)
{
    __shared__ float As[8][132];   // transposed A tile, padded (132 % 4 == 0)
    __shared__ float Bs[8][128];

    int tid = threadIdx.x;
    int tx  = tid & 15;            // 0..15 -> col group
    int ty  = tid >> 4;            // 0..15 -> row group
    int rowTile = blockIdx.y * 128;
    int colTile = blockIdx.x * 128;

    // loader mapping
    int arow = tid >> 1;           // 0..127
    int aseg = (tid & 1) * 4;      // 0 or 4
    int bkr  = tid >> 5;           // 0..7
    int bcol = (tid & 31) * 4;     // 0..124

    const float* Aptr = A + (size_t)(rowTile + arow) * K + aseg;
    const float* Bptr = W + (size_t)bkr * Nc + colTile + bcol;

    float acc[8][8];
#pragma unroll
    for (int i = 0; i < 8; i++)
#pragma unroll
        for (int j = 0; j < 8; j++) acc[i][j] = 0.f;

    for (int kt = 0; kt < K; kt += 8) {
        float4 av = *(const float4*)(Aptr + kt);
        float4 bv = *(const float4*)(Bptr + (size_t)kt * Nc);
        As[aseg + 0][arow] = av.x;
        As[aseg + 1][arow] = av.y;
        As[aseg + 2][arow] = av.z;
        As[aseg + 3][arow] = av.w;
        *(float4*)&Bs[bkr][bcol] = bv;
        __syncthreads();
#pragma unroll
        for (int kk = 0; kk < 8; kk++) {
            float a[8], b[8];
            *(float4*)(a)     = *(const float4*)&As[kk][ty * 8];
            *(float4*)(a + 4) = *(const float4*)&As[kk][ty * 8 + 4];
            *(float4*)(b)     = *(const float4*)&Bs[kk][tx * 8];
            *(float4*)(b + 4) = *(const float4*)&Bs[kk][tx * 8 + 4];
#pragma unroll
            for (int i = 0; i < 8; i++)
#pragma unroll
                for (int j = 0; j < 8; j++)
                    acc[i][j] += a[i] * b[j];
        }
        __syncthreads();
    }

    // epilogue
#pragma unroll
    for (int i = 0; i < 8; i++) {
        float* crow = Cc + (size_t)(rowTile + ty * 8 + i) * Nc + colTile + tx * 8;
#pragma unroll
        for (int j = 0; j < 8; j += 4) {
            float4 o;
            o.x = acc[i][j + 0] + bias[colTile + tx * 8 + j + 0];
            o.y = acc[i][j + 1] + bias[colTile + tx * 8 + j + 1];
            o.z = acc[i][j + 2] + bias[colTile + tx * 8 + j + 2];
            o.w = acc[i][j + 3] + bias[colTile + tx * 8 + j + 3];
            if (RELU) {
                o.x = fmaxf(o.x, 0.f); o.y = fmaxf(o.y, 0.f);
                o.z = fmaxf(o.z, 0.f); o.w = fmaxf(o.w, 0.f);
            }
            *(float4*)(crow + j) = o;
        }
    }
}

// ---------------------------------------------------------------------------
// vsum[b,h,d] = sum_n v[b,h,n,d]
// ---------------------------------------------------------------------------
__global__ __launch_bounds__(256) void vsum_kernel(float* __restrict__ vs)
{
    __shared__ float red[256];
    int bh = blockIdx.x;             // 0..63
    int b = bh >> 3, h = bh & 7;
    int tid = threadIdx.x;
    int d = tid & 63, chunk = tid >> 6;   // 4 chunks of 256 rows

    size_t base = ((size_t)b * N_) * KV_C + C_ + (size_t)h * D_ + d;
    float s = 0.f;
    int n0 = chunk * 256;
    for (int n = n0; n < n0 + 256; n++)
        s += g_kv[base + (size_t)n * KV_C];
    red[tid] = s;
    __syncthreads();
    if (chunk == 0)
        vs[bh * 64 + d] = red[d] + red[d + 64] + red[d + 128] + red[d + 192];
}

// ---------------------------------------------------------------------------
// Fused attention: scores (q@k^T), top-16 selection, closed-form sparse
// softmax, sparse @ v via gather + vsum. Block = (b,h) x 16 query rows.
// ---------------------------------------------------------------------------
#define ROWS 16
#define SC_PAD 1028               // scores row pitch (mult of 4)
#define KST_PAD 132               // kst row pitch (mult of 4)
#define ATTN_SMEM_FLOATS (ROWS*64 + 64*KST_PAD + ROWS*SC_PAD + ROWS*16 + ROWS*16 + ROWS + ROWS*16)
#define ATTN_SMEM_BYTES (ATTN_SMEM_FLOATS * 4)

__global__ __launch_bounds__(256) void attn_kernel(float* __restrict__ out,
                                                   const float* __restrict__ vs)
{
    extern __shared__ float sm[];
    float* qs     = sm;                         // [16][64]
    float* kst    = qs + ROWS * 64;             // [64][132]  (kst[d][m])
    float* scores = kst + 64 * KST_PAD;         // [16][1028]
    float* topv   = scores + ROWS * SC_PAD;     // [16][16]
    float* wsh    = topv + ROWS * 16;           // [16][16]  (w_i - c)/Z
    float* csh    = wsh + ROWS * 16;            // [16]      c/Z
    int*   topi   = (int*)(csh + ROWS);         // [16][16]

    int bh = blockIdx.y;                        // 0..63
    int b = bh >> 3, h = bh & 7;
    int n0 = blockIdx.x * ROWS;
    int tid = threadIdx.x;
    int tr = tid >> 5;                          // 0..7 -> rows {2tr, 2tr+1}
    int tm = tid & 31;                          // 0..31 -> cols {4tm..4tm+3}
    const float scale = 0.125f;                 // 1/sqrt(64)

    // load 16 q rows
    {
        size_t qbase = ((size_t)(b * N_ + n0)) * C_ + (size_t)h * D_;
        for (int f = tid; f < ROWS * 64; f += 256) {
            int r = f >> 6, d = f & 63;
            qs[f] = g_q[qbase + (size_t)r * C_ + d];
        }
    }

    size_t kbase = ((size_t)b * N_) * KV_C + (size_t)h * D_;

    // ---- scores GEMM: 8 tiles of 128 keys ----
    for (int mt = 0; mt < N_; mt += 128) {
        __syncthreads();
        for (int g = tid; g < 128 * 16; g += 256) {
            int m = g >> 4, d4 = (g & 15) * 4;
            float4 kv4 = *(const float4*)&g_kv[kbase + (size_t)(mt + m) * KV_C + d4];
            kst[(d4 + 0) * KST_PAD + m] = kv4.x;
            kst[(d4 + 1) * KST_PAD + m] = kv4.y;
            kst[(d4 + 2) * KST_PAD + m] = kv4.z;
            kst[(d4 + 3) * KST_PAD + m] = kv4.w;
        }
        __syncthreads();

        const float* q0 = qs + (2 * tr) * 64;
        const float* q1 = q0 + 64;
        float a00 = 0, a01 = 0, a02 = 0, a03 = 0;
        float a10 = 0, a11 = 0, a12 = 0, a13 = 0;
#pragma unroll
        for (int d = 0; d < 64; d++) {
            float4 kv4 = *(const float4*)&kst[d * KST_PAD + tm * 4];
            float x0 = q0[d], x1 = q1[d];
            a00 += x0 * kv4.x; a01 += x0 * kv4.y; a02 += x0 * kv4.z; a03 += x0 * kv4.w;
            a10 += x1 * kv4.x; a11 += x1 * kv4.y; a12 += x1 * kv4.z; a13 += x1 * kv4.w;
        }
        *(float4*)&scores[(2 * tr) * SC_PAD + mt + tm * 4] =
            make_float4(a00 * scale, a01 * scale, a02 * scale, a03 * scale);
        *(float4*)&scores[(2 * tr + 1) * SC_PAD + mt + tm * 4] =
            make_float4(a10 * scale, a11 * scale, a12 * scale, a13 * scale);
    }
    __syncthreads();

    // ---- top-16 per row (register-resident iterative argmax) ----
    int lane = tid & 31;
    for (int rr = 2 * tr; rr <= 2 * tr + 1; rr++) {
        const float* srow = scores + rr * SC_PAD;
        float v[32];
#pragma unroll
        for (int j = 0; j < 32; j++) v[j] = srow[lane + 32 * j];

        float m0 = 0.f;
        for (int it = 0; it < TOPK; it++) {
            float bv = v[0]; int bj = 0;
#pragma unroll
            for (int j = 1; j < 32; j++)
                if (v[j] > bv) { bv = v[j]; bj = j; }
            int bidx = lane + 32 * bj;
#pragma unroll
            for (int off = 16; off; off >>= 1) {
                float ov = __shfl_xor_sync(0xffffffffu, bv, off);
                int   oi = __shfl_xor_sync(0xffffffffu, bidx, off);
                if (ov > bv || (ov == bv && oi < bidx)) { bv = ov; bidx = oi; }
            }
            if (it == 0) m0 = bv;
            if (lane == 0) { topv[rr * 16 + it] = bv; topi[rr * 16 + it] = bidx; }
            if (lane == (bidx & 31)) {
                int jj = bidx >> 5;
#pragma unroll
                for (int j = 0; j < 32; j++)
                    if (j == jj) v[j] = -CUDART_INF_F;
            }
        }
        __syncwarp();

        // closed-form sparse softmax weights
        float Mx = fmaxf(0.f, m0);
        float c  = expf(-Mx);
        float wv = (lane < TOPK) ? expf(topv[rr * 16 + lane] - Mx) : 0.f;
        float s = wv;
#pragma unroll
        for (int off = 16; off; off >>= 1)
            s += __shfl_xor_sync(0xffffffffu, s, off);
        float Z = s + (float)(N_ - TOPK) * c;
        if (lane < TOPK) wsh[rr * 16 + lane] = (wv - c) / Z;
        if (lane == 0)   csh[rr] = c / Z;
    }
    __syncthreads();

    // ---- epilogue: out[n,d] = sum_i wsh_i * v[idx_i,d] + (c/Z)*vsum[d] ----
    {
        int r = tid >> 4, q16 = tid & 15;       // 16 threads per row, 4 d each
        size_t vbase = ((size_t)b * N_) * KV_C + C_ + (size_t)h * D_ + q16 * 4;
        float4 o = make_float4(0, 0, 0, 0);
#pragma unroll
        for (int i = 0; i < TOPK; i++) {
            int   idx = topi[r * 16 + i];
            float w   = wsh[r * 16 + i];
            float4 vv = *(const float4*)&g_kv[vbase + (size_t)idx * KV_C];
            o.x += w * vv.x; o.y += w * vv.y; o.z += w * vv.z; o.w += w * vv.w;
        }
        float cz = csh[r];
        float4 vsv = *(const float4*)&vs[bh * 64 + q16 * 4];
        o.x += cz * vsv.x; o.y += cz * vsv.y; o.z += cz * vsv.z; o.w += cz * vsv.w;
        *(float4*)&out[((size_t)(b * N_ + n0 + r)) * C_ + (size_t)h * D_ + q16 * 4] = o;
    }
}

// ---------------------------------------------------------------------------
extern "C" void kernel_launch(void* const* d_in, const int* in_sizes, int n_in,
                              void* d_out, int out_size)
{
    const float* x   = (const float*)d_in[0];
    const float* Wq  = (const float*)d_in[1];
    const float* bq  = (const float*)d_in[2];
    const float* Wkv = (const float*)d_in[3];
    const float* bkv = (const float*)d_in[4];
    const float* Wp  = (const float*)d_in[5];
    const float* bp  = (const float*)d_in[6];
    float* out = (float*)d_out;

    float *gq, *gkv, *gatt, *gvs;
    cudaGetSymbolAddress((void**)&gq,  g_q);
    cudaGetSymbolAddress((void**)&gkv, g_kv);
    cudaGetSymbolAddress((void**)&gatt, g_att);
    cudaGetSymbolAddress((void**)&gvs, g_vsum);

    // 1. Q = relu(x @ Wq + bq)
    gemm_kernel<true><<<dim3(C_ / 128, M_ / 128), 256>>>(x, Wq, bq, gq, C_, C_);
    // 2. KV = x @ Wkv + bkv
    gemm_kernel<false><<<dim3(KV_C / 128, M_ / 128), 256>>>(x, Wkv, bkv, gkv, C_, KV_C);
    // 3. vsum
    vsum_kernel<<<B_ * H_, 256>>>(gvs);
    // 4. fused scores + topk + sparse softmax + gather
    cudaFuncSetAttribute(attn_kernel, cudaFuncAttributeMaxDynamicSharedMemorySize,
                         ATTN_SMEM_BYTES);
    attn_kernel<<<dim3(N_ / ROWS, B_ * H_), 256, ATTN_SMEM_BYTES>>>(gatt, gvs);
    // 5. out = att @ Wp + bp
    gemm_kernel<false><<<dim3(C_ / 128, M_ / 128), 256>>>(gatt, Wp, bp, out, C_, C_);
}

// round 5
// speedup vs baseline: 1.1264x; 1.1264x over previous
#include <cuda_runtime.h>

#define B_   8
#define N_   1024
#define C_   512
#define H_   8
#define D_   64
#define TOPK 16
#define M_   (B_ * N_)          // 8192 rows
#define KV_C (2 * C_)           // 1024

// Scratch (device globals; no allocation allowed)
__device__ float g_q[M_ * C_];          // relu(x@Wq+bq)
__device__ float g_kv[M_ * KV_C];       // x@Wkv+bkv  (k at col [0,512), v at [512,1024))
__device__ float g_att[M_ * C_];        // attention output (pre-projection)
__device__ float g_vsum[B_ * H_ * D_];  // per-(b,h) column sums of v

// ---------------------------------------------------------------------------
// Tiled fp32 GEMM: C = act(A[M,K] @ W[K,Nc] + bias), 128x128 tile, BK=8,
// 256 threads, 8x8 microtile per thread. (At fp32 FMA roofline — unchanged.)
// ---------------------------------------------------------------------------
template <bool RELU>
__global__ __launch_bounds__(256) void gemm_kernel(
    const float* __restrict__ A, const float* __restrict__ W,
    const float* __restrict__ bias, float* __restrict__ Cc, int K, int Nc)
{
    __shared__ float As[8][132];
    __shared__ float Bs[8][128];

    int tid = threadIdx.x;
    int tx  = tid & 15;
    int ty  = tid >> 4;
    int rowTile = blockIdx.y * 128;
    int colTile = blockIdx.x * 128;

    int arow = tid >> 1;
    int aseg = (tid & 1) * 4;
    int bkr  = tid >> 5;
    int bcol = (tid & 31) * 4;

    const float* Aptr = A + (size_t)(rowTile + arow) * K + aseg;
    const float* Bptr = W + (size_t)bkr * Nc + colTile + bcol;

    float acc[8][8];
#pragma unroll
    for (int i = 0; i < 8; i++)
#pragma unroll
        for (int j = 0; j < 8; j++) acc[i][j] = 0.f;

    for (int kt = 0; kt < K; kt += 8) {
        float4 av = *(const float4*)(Aptr + kt);
        float4 bv = *(const float4*)(Bptr + (size_t)kt * Nc);
        As[aseg + 0][arow] = av.x;
        As[aseg + 1][arow] = av.y;
        As[aseg + 2][arow] = av.z;
        As[aseg + 3][arow] = av.w;
        *(float4*)&Bs[bkr][bcol] = bv;
        __syncthreads();
#pragma unroll
        for (int kk = 0; kk < 8; kk++) {
            float a[8], b[8];
            *(float4*)(a)     = *(const float4*)&As[kk][ty * 8];
            *(float4*)(a + 4) = *(const float4*)&As[kk][ty * 8 + 4];
            *(float4*)(b)     = *(const float4*)&Bs[kk][tx * 8];
            *(float4*)(b + 4) = *(const float4*)&Bs[kk][tx * 8 + 4];
#pragma unroll
            for (int i = 0; i < 8; i++)
#pragma unroll
                for (int j = 0; j < 8; j++)
                    acc[i][j] += a[i] * b[j];
        }
        __syncthreads();
    }

#pragma unroll
    for (int i = 0; i < 8; i++) {
        float* crow = Cc + (size_t)(rowTile + ty * 8 + i) * Nc + colTile + tx * 8;
#pragma unroll
        for (int j = 0; j < 8; j += 4) {
            float4 o;
            o.x = acc[i][j + 0] + bias[colTile + tx * 8 + j + 0];
            o.y = acc[i][j + 1] + bias[colTile + tx * 8 + j + 1];
            o.z = acc[i][j + 2] + bias[colTile + tx * 8 + j + 2];
            o.w = acc[i][j + 3] + bias[colTile + tx * 8 + j + 3];
            if (RELU) {
                o.x = fmaxf(o.x, 0.f); o.y = fmaxf(o.y, 0.f);
                o.z = fmaxf(o.z, 0.f); o.w = fmaxf(o.w, 0.f);
            }
            *(float4*)(crow + j) = o;
        }
    }
}

// ---------------------------------------------------------------------------
// vsum[b,h,d] = sum_n v[b,h,n,d]
// ---------------------------------------------------------------------------
__global__ __launch_bounds__(256) void vsum_kernel(float* __restrict__ vs)
{
    __shared__ float red[256];
    int bh = blockIdx.x;
    int b = bh >> 3, h = bh & 7;
    int tid = threadIdx.x;
    int d = tid & 63, chunk = tid >> 6;

    size_t base = ((size_t)b * N_) * KV_C + C_ + (size_t)h * D_ + d;
    float s = 0.f;
    int n0 = chunk * 256;
    for (int n = n0; n < n0 + 256; n++)
        s += g_kv[base + (size_t)n * KV_C];
    red[tid] = s;
    __syncthreads();
    if (chunk == 0)
        vs[bh * 64 + d] = red[d] + red[d + 64] + red[d + 128] + red[d + 192];
}

// ---------------------------------------------------------------------------
// Full-precision monotonic float<->uint mapping (bijective, order-preserving).
// ---------------------------------------------------------------------------
__device__ __forceinline__ unsigned mono_pack(float s)
{
    unsigned b = __float_as_uint(s);
    return b ^ (unsigned)(((int)b >> 31) | 0x80000000);
}
__device__ __forceinline__ float mono_unpack(unsigned u)
{
    unsigned b = (u & 0x80000000u) ? (u ^ 0x80000000u) : ~u;
    return __uint_as_float(b);
}

// ---------------------------------------------------------------------------
// Fused attention: scores (q@k^T) with register-cached q, top-16 via
// REDUX.MAX.U32 on (mono_key & ~31 | reg_slot) — only 5 key bits sacrificed;
// exact scores refetched from smem for the softmax weights. Closed-form
// sparse softmax + gather/vsum epilogue. Block = (b,h) x 16 rows, 256 thr.
// ---------------------------------------------------------------------------
#define ROWS 16
#define KST_PAD 132
// smem (floats): qs[16*64] kst[64*132] scoresU[16*1024] wsh[256] csh[16] topi[256]
#define ATTN_SMEM_FLOATS (ROWS*64 + 64*KST_PAD + ROWS*1024 + ROWS*16 + ROWS + ROWS*16)
#define ATTN_SMEM_BYTES (ATTN_SMEM_FLOATS * 4)

__global__ __launch_bounds__(256) void attn_kernel(float* __restrict__ out,
                                                   const float* __restrict__ vs)
{
    extern __shared__ float sm[];
    float*    qs      = sm;                       // [16][64]
    float*    kst     = qs + ROWS * 64;           // [64][132] (kst[d][m])
    unsigned* scoresU = (unsigned*)(kst + 64 * KST_PAD);  // [16][1024] full mono
    float*    wsh     = (float*)(scoresU + ROWS * 1024);  // [16][16]
    float*    csh     = wsh + ROWS * 16;          // [16]
    int*      topi    = (int*)(csh + ROWS);       // [16][16]

    int bh = blockIdx.y;
    int b = bh >> 3, h = bh & 7;
    int n0 = blockIdx.x * ROWS;
    int tid = threadIdx.x;
    int tr = tid >> 5;            // 0..7 -> rows {2tr, 2tr+1}
    int tm = tid & 31;            // 0..31 -> key cols {4tm..4tm+3}
    int lane = tid & 31;
    const float scale = 0.125f;

    // load 16 q rows
    {
        size_t qbase = ((size_t)(b * N_ + n0)) * C_ + (size_t)h * D_;
        for (int f = tid; f < ROWS * 64; f += 256) {
            int r = f >> 6, d = f & 63;
            qs[f] = g_q[qbase + (size_t)r * C_ + d];
        }
    }

    size_t kbase = ((size_t)b * N_) * KV_C + (size_t)h * D_;

    // ---- scores GEMM: 8 tiles of 128 keys, q register-cached per 16-d chunk ----
    for (int mt = 0; mt < N_; mt += 128) {
        __syncthreads();
        for (int g = tid; g < 128 * 16; g += 256) {
            int m = g >> 4, d4 = (g & 15) * 4;
            float4 kv4 = *(const float4*)&g_kv[kbase + (size_t)(mt + m) * KV_C + d4];
            kst[(d4 + 0) * KST_PAD + m] = kv4.x;
            kst[(d4 + 1) * KST_PAD + m] = kv4.y;
            kst[(d4 + 2) * KST_PAD + m] = kv4.z;
            kst[(d4 + 3) * KST_PAD + m] = kv4.w;
        }
        __syncthreads();

        const float* q0 = qs + (2 * tr) * 64;
        const float* q1 = q0 + 64;
        float a00 = 0, a01 = 0, a02 = 0, a03 = 0;
        float a10 = 0, a11 = 0, a12 = 0, a13 = 0;
#pragma unroll
        for (int dc = 0; dc < 64; dc += 16) {
            float q0r[16], q1r[16];
#pragma unroll
            for (int t = 0; t < 16; t += 4) {
                *(float4*)&q0r[t] = *(const float4*)&q0[dc + t];  // warp-broadcast
                *(float4*)&q1r[t] = *(const float4*)&q1[dc + t];
            }
#pragma unroll
            for (int dd = 0; dd < 16; dd++) {
                float4 k4 = *(const float4*)&kst[(dc + dd) * KST_PAD + tm * 4];
                float x0 = q0r[dd], x1 = q1r[dd];
                a00 += x0 * k4.x; a01 += x0 * k4.y; a02 += x0 * k4.z; a03 += x0 * k4.w;
                a10 += x1 * k4.x; a11 += x1 * k4.y; a12 += x1 * k4.z; a13 += x1 * k4.w;
            }
        }
        unsigned col = (unsigned)(mt + tm * 4);
        uint4 p0, p1;
        p0.x = mono_pack(a00 * scale); p0.y = mono_pack(a01 * scale);
        p0.z = mono_pack(a02 * scale); p0.w = mono_pack(a03 * scale);
        p1.x = mono_pack(a10 * scale); p1.y = mono_pack(a11 * scale);
        p1.z = mono_pack(a12 * scale); p1.w = mono_pack(a13 * scale);
        *(uint4*)&scoresU[(2 * tr) * 1024 + col]     = p0;
        *(uint4*)&scoresU[(2 * tr + 1) * 1024 + col] = p1;
    }
    __syncthreads();

    // ---- top-16 per row: uint argmax, 5 low key bits carry the reg slot ----
    for (int rr = 2 * tr; rr <= 2 * tr + 1; rr++) {
        const unsigned* srow = scoresU + rr * 1024;
        unsigned v[32];
#pragma unroll
        for (int j = 0; j < 32; j++)
            v[j] = (srow[lane + 32 * j] & ~31u) | (unsigned)j;   // conflict-free

#pragma unroll
        for (int it = 0; it < TOPK; it++) {
            unsigned lm = v[0];
#pragma unroll
            for (int j = 1; j < 32; j++) lm = max(lm, v[j]);
            unsigned gm = __reduce_max_sync(0xffffffffu, lm);
            unsigned ball = __ballot_sync(0xffffffffu, lm == gm);
            int wl = __ffs(ball) - 1;                    // deterministic winner
            if (lane == wl) {
                int jj = (int)(gm & 31u);
                topi[rr * 16 + it] = lane + 32 * jj;
#pragma unroll
                for (int j = 0; j < 32; j++)
                    if (j == jj) v[j] = 0u;
            }
        }
        __syncwarp();

        // exact-score softmax weights (closed form for the masked softmax)
        float sv = 0.f;
        int   idx = 0;
        if (lane < TOPK) {
            idx = topi[rr * 16 + lane];
            sv  = mono_unpack(srow[idx]);                // exact fp32 score
        }
        float s0 = __shfl_sync(0xffffffffu, sv, 0);      // top-1 exact
        float Mx = fmaxf(0.f, s0);
        float c  = expf(-Mx);
        float w  = (lane < TOPK) ? expf(sv - Mx) : 0.f;
        float s = w;
#pragma unroll
        for (int off = 16; off; off >>= 1)
            s += __shfl_xor_sync(0xffffffffu, s, off);
        float Z = s + (float)(N_ - TOPK) * c;
        if (lane < TOPK) wsh[rr * 16 + lane] = (w - c) / Z;
        if (lane == 0)   csh[rr] = c / Z;
    }
    __syncthreads();

    // ---- epilogue: out[n,d] = sum_i wsh_i * v[idx_i,d] + (c/Z)*vsum[d] ----
    {
        int r = tid >> 4, q16 = tid & 15;
        size_t vbase = ((size_t)b * N_) * KV_C + C_ + (size_t)h * D_ + q16 * 4;
        float4 o = make_float4(0, 0, 0, 0);
#pragma unroll
        for (int i = 0; i < TOPK; i++) {
            int   idx = topi[r * 16 + i];
            float w   = wsh[r * 16 + i];
            float4 vv = *(const float4*)&g_kv[vbase + (size_t)idx * KV_C];
            o.x += w * vv.x; o.y += w * vv.y; o.z += w * vv.z; o.w += w * vv.w;
        }
        float cz = csh[r];
        float4 vsv = *(const float4*)&vs[bh * 64 + q16 * 4];
        o.x += cz * vsv.x; o.y += cz * vsv.y; o.z += cz * vsv.z; o.w += cz * vsv.w;
        *(float4*)&out[((size_t)(b * N_ + n0 + r)) * C_ + (size_t)h * D_ + q16 * 4] = o;
    }
}

// ---------------------------------------------------------------------------
extern "C" void kernel_launch(void* const* d_in, const int* in_sizes, int n_in,
                              void* d_out, int out_size)
{
    const float* x   = (const float*)d_in[0];
    const float* Wq  = (const float*)d_in[1];
    const float* bq  = (const float*)d_in[2];
    const float* Wkv = (const float*)d_in[3];
    const float* bkv = (const float*)d_in[4];
    const float* Wp  = (const float*)d_in[5];
    const float* bp  = (const float*)d_in[6];
    float* out = (float*)d_out;

    float *gq, *gkv, *gatt, *gvs;
    cudaGetSymbolAddress((void**)&gq,  g_q);
    cudaGetSymbolAddress((void**)&gkv, g_kv);
    cudaGetSymbolAddress((void**)&gatt, g_att);
    cudaGetSymbolAddress((void**)&gvs, g_vsum);

    // 1. Q = relu(x @ Wq + bq)
    gemm_kernel<true><<<dim3(C_ / 128, M_ / 128), 256>>>(x, Wq, bq, gq, C_, C_);
    // 2. KV = x @ Wkv + bkv
    gemm_kernel<false><<<dim3(KV_C / 128, M_ / 128), 256>>>(x, Wkv, bkv, gkv, C_, KV_C);
    // 3. vsum
    vsum_kernel<<<B_ * H_, 256>>>(gvs);
    // 4. fused scores + topk + sparse softmax + gather
    cudaFuncSetAttribute(attn_kernel, cudaFuncAttributeMaxDynamicSharedMemorySize,
                         ATTN_SMEM_BYTES);
    attn_kernel<<<dim3(N_ / ROWS, B_ * H_), 256, ATTN_SMEM_BYTES>>>(gatt, gvs);
    // 5. out = att @ Wp + bp
    gemm_kernel<false><<<dim3(C_ / 128, M_ / 128), 256>>>(gatt, Wp, bp, out, C_, C_);
}

// round 6
// speedup vs baseline: 1.1377x; 1.0101x over previous
#include <cuda_runtime.h>

#define B_   8
#define N_   1024
#define C_   512
#define H_   8
#define D_   64
#define TOPK 16
#define M_   (B_ * N_)          // 8192 rows
#define KV_C (2 * C_)           // 1024

// Scratch (device globals; no allocation allowed)
__device__ float g_q[M_ * C_];          // relu(x@Wq+bq)
__device__ float g_kv[M_ * KV_C];       // x@Wkv+bkv  (k at col [0,512), v at [512,1024))
__device__ float g_att[M_ * C_];        // attention output (pre-projection)
__device__ float g_vsum[B_ * H_ * D_];  // per-(b,h) column sums of v

// ---------------------------------------------------------------------------
// Tiled fp32 GEMM: C = act(A[M,K] @ W[K,Nc] + bias). At FFMA roofline.
// ---------------------------------------------------------------------------
template <bool RELU>
__global__ __launch_bounds__(256) void gemm_kernel(
    const float* __restrict__ A, const float* __restrict__ W,
    const float* __restrict__ bias, float* __restrict__ Cc, int K, int Nc)
{
    __shared__ float As[8][132];
    __shared__ float Bs[8][128];

    int tid = threadIdx.x;
    int tx  = tid & 15;
    int ty  = tid >> 4;
    int rowTile = blockIdx.y * 128;
    int colTile = blockIdx.x * 128;

    int arow = tid >> 1;
    int aseg = (tid & 1) * 4;
    int bkr  = tid >> 5;
    int bcol = (tid & 31) * 4;

    const float* Aptr = A + (size_t)(rowTile + arow) * K + aseg;
    const float* Bptr = W + (size_t)bkr * Nc + colTile + bcol;

    float acc[8][8];
#pragma unroll
    for (int i = 0; i < 8; i++)
#pragma unroll
        for (int j = 0; j < 8; j++) acc[i][j] = 0.f;

    for (int kt = 0; kt < K; kt += 8) {
        float4 av = *(const float4*)(Aptr + kt);
        float4 bv = *(const float4*)(Bptr + (size_t)kt * Nc);
        As[aseg + 0][arow] = av.x;
        As[aseg + 1][arow] = av.y;
        As[aseg + 2][arow] = av.z;
        As[aseg + 3][arow] = av.w;
        *(float4*)&Bs[bkr][bcol] = bv;
        __syncthreads();
#pragma unroll
        for (int kk = 0; kk < 8; kk++) {
            float a[8], b[8];
            *(float4*)(a)     = *(const float4*)&As[kk][ty * 8];
            *(float4*)(a + 4) = *(const float4*)&As[kk][ty * 8 + 4];
            *(float4*)(b)     = *(const float4*)&Bs[kk][tx * 8];
            *(float4*)(b + 4) = *(const float4*)&Bs[kk][tx * 8 + 4];
#pragma unroll
            for (int i = 0; i < 8; i++)
#pragma unroll
                for (int j = 0; j < 8; j++)
                    acc[i][j] += a[i] * b[j];
        }
        __syncthreads();
    }

#pragma unroll
    for (int i = 0; i < 8; i++) {
        float* crow = Cc + (size_t)(rowTile + ty * 8 + i) * Nc + colTile + tx * 8;
#pragma unroll
        for (int j = 0; j < 8; j += 4) {
            float4 o;
            o.x = acc[i][j + 0] + bias[colTile + tx * 8 + j + 0];
            o.y = acc[i][j + 1] + bias[colTile + tx * 8 + j + 1];
            o.z = acc[i][j + 2] + bias[colTile + tx * 8 + j + 2];
            o.w = acc[i][j + 3] + bias[colTile + tx * 8 + j + 3];
            if (RELU) {
                o.x = fmaxf(o.x, 0.f); o.y = fmaxf(o.y, 0.f);
                o.z = fmaxf(o.z, 0.f); o.w = fmaxf(o.w, 0.f);
            }
            *(float4*)(crow + j) = o;
        }
    }
}

// ---------------------------------------------------------------------------
// vsum[b,h,d] = sum_n v[b,h,n,d]
// ---------------------------------------------------------------------------
__global__ __launch_bounds__(256) void vsum_kernel(float* __restrict__ vs)
{
    __shared__ float red[256];
    int bh = blockIdx.x;
    int b = bh >> 3, h = bh & 7;
    int tid = threadIdx.x;
    int d = tid & 63, chunk = tid >> 6;

    size_t base = ((size_t)b * N_) * KV_C + C_ + (size_t)h * D_ + d;
    float s = 0.f;
    int n0 = chunk * 256;
    for (int n = n0; n < n0 + 256; n++)
        s += g_kv[base + (size_t)n * KV_C];
    red[tid] = s;
    __syncthreads();
    if (chunk == 0)
        vs[bh * 64 + d] = red[d] + red[d + 64] + red[d + 128] + red[d + 192];
}

// ---------------------------------------------------------------------------
// Full-precision monotonic float<->uint mapping (bijective, order-preserving).
// ---------------------------------------------------------------------------
__device__ __forceinline__ unsigned mono_pack(float s)
{
    unsigned b = __float_as_uint(s);
    return b ^ (unsigned)(((int)b >> 31) | 0x80000000);
}
__device__ __forceinline__ float mono_unpack(unsigned u)
{
    unsigned b = (u & 0x80000000u) ? (u ^ 0x80000000u) : ~u;
    return __uint_as_float(b);
}

// ---------------------------------------------------------------------------
// Fused attention v3: ROWS=32 per block, qT broadcast layout, 4x4 microtile
// -> FMA-bound scores GEMM. Exact top-16 (mono-uint keys, 5-bit slot),
// closed-form sparse softmax, gather + vsum epilogue. 256 thr, 1 blk/SM.
// ---------------------------------------------------------------------------
#define ROWS 32
#define QT_PITCH 33
#define KST_PITCH 132
// smem floats: qT[64*33] kst[64*132] scoresU[32*1024] wsh[32*16] csh[32] topi[32*16]
#define ATTN_SMEM_FLOATS (64*QT_PITCH + 64*KST_PITCH + ROWS*1024 + ROWS*16 + ROWS + ROWS*16)
#define ATTN_SMEM_BYTES (ATTN_SMEM_FLOATS * 4)

__global__ __launch_bounds__(256, 1) void attn_kernel(float* __restrict__ out,
                                                      const float* __restrict__ vs)
{
    extern __shared__ float sm[];
    float*    qT      = sm;                              // [64][33]  qT[d][r]
    float*    kst     = qT + 64 * QT_PITCH;              // [64][132] kst[d][m]
    unsigned* scoresU = (unsigned*)(kst + 64 * KST_PITCH); // [32][1024]
    float*    wsh     = (float*)(scoresU + ROWS * 1024); // [32][16]
    float*    csh     = wsh + ROWS * 16;                 // [32]
    int*      topi    = (int*)(csh + ROWS);              // [32][16]

    int bh = blockIdx.y;
    int b = bh >> 3, h = bh & 7;
    int n0 = blockIdx.x * ROWS;
    int tid = threadIdx.x;
    int w    = tid >> 5;          // warp 0..7 -> rows 4w..4w+3
    int lane = tid & 31;          // cols 4*lane..4*lane+3 per tile
    const float scale = 0.125f;

    // ---- load 32 q rows transposed: qT[d][r] (coalesced LDG, cf-free STS) ----
    {
        size_t qbase = ((size_t)(b * N_ + n0)) * C_ + (size_t)h * D_;
        for (int f = tid; f < ROWS * 64; f += 256) {
            int r = f >> 6, d = f & 63;
            qT[d * QT_PITCH + r] = g_q[qbase + (size_t)r * C_ + d];
        }
    }

    size_t kbase = ((size_t)b * N_) * KV_C + (size_t)h * D_;

    // k-tile element mapping: per thread 8 float4; g = tid + 256*i:
    //   m = g & 127 (key within tile), d4 = (g >> 7) * 4
    float4 pf[8];
#pragma unroll
    for (int i = 0; i < 8; i++) {
        int g = tid + 256 * i;
        int m = g & 127, d4 = (g >> 7) * 4;
        pf[i] = *(const float4*)&g_kv[kbase + (size_t)m * KV_C + d4];
    }

    for (int mt = 0; mt < N_; mt += 128) {
        __syncthreads();   // previous tile's compute done reading kst
#pragma unroll
        for (int i = 0; i < 8; i++) {
            int g = tid + 256 * i;
            int m = g & 127, d4 = (g >> 7) * 4;
            kst[(d4 + 0) * KST_PITCH + m] = pf[i].x;   // lanes -> consecutive m: cf-free
            kst[(d4 + 1) * KST_PITCH + m] = pf[i].y;
            kst[(d4 + 2) * KST_PITCH + m] = pf[i].z;
            kst[(d4 + 3) * KST_PITCH + m] = pf[i].w;
        }
        __syncthreads();

        if (mt + 128 < N_) {   // prefetch next tile into registers
#pragma unroll
            for (int i = 0; i < 8; i++) {
                int g = tid + 256 * i;
                int m = g & 127, d4 = (g >> 7) * 4;
                pf[i] = *(const float4*)&g_kv[kbase + (size_t)(mt + 128 + m) * KV_C + d4];
            }
        }

        // ---- 4 rows x 4 cols per thread; q via smem broadcast ----
        float a00=0,a01=0,a02=0,a03=0, a10=0,a11=0,a12=0,a13=0;
        float a20=0,a21=0,a22=0,a23=0, a30=0,a31=0,a32=0,a33=0;
        const float* qTw = qT + 4 * w;
#pragma unroll 8
        for (int d = 0; d < 64; d++) {
            float4 k4 = *(const float4*)&kst[d * KST_PITCH + 4 * lane];
            float q0 = qTw[d * QT_PITCH + 0];
            float q1 = qTw[d * QT_PITCH + 1];
            float q2 = qTw[d * QT_PITCH + 2];
            float q3 = qTw[d * QT_PITCH + 3];
            a00 += q0*k4.x; a01 += q0*k4.y; a02 += q0*k4.z; a03 += q0*k4.w;
            a10 += q1*k4.x; a11 += q1*k4.y; a12 += q1*k4.z; a13 += q1*k4.w;
            a20 += q2*k4.x; a21 += q2*k4.y; a22 += q2*k4.z; a23 += q2*k4.w;
            a30 += q3*k4.x; a31 += q3*k4.y; a32 += q3*k4.z; a33 += q3*k4.w;
        }
        unsigned col = (unsigned)(mt + 4 * lane);
        uint4 p;
        p.x = mono_pack(a00*scale); p.y = mono_pack(a01*scale);
        p.z = mono_pack(a02*scale); p.w = mono_pack(a03*scale);
        *(uint4*)&scoresU[(4*w + 0) * 1024 + col] = p;
        p.x = mono_pack(a10*scale); p.y = mono_pack(a11*scale);
        p.z = mono_pack(a12*scale); p.w = mono_pack(a13*scale);
        *(uint4*)&scoresU[(4*w + 1) * 1024 + col] = p;
        p.x = mono_pack(a20*scale); p.y = mono_pack(a21*scale);
        p.z = mono_pack(a22*scale); p.w = mono_pack(a23*scale);
        *(uint4*)&scoresU[(4*w + 2) * 1024 + col] = p;
        p.x = mono_pack(a30*scale); p.y = mono_pack(a31*scale);
        p.z = mono_pack(a32*scale); p.w = mono_pack(a33*scale);
        *(uint4*)&scoresU[(4*w + 3) * 1024 + col] = p;
    }
    __syncthreads();

    // ---- top-16 per row: uint argmax, 5 low key bits carry the reg slot ----
    for (int rr = 4 * w; rr < 4 * w + 4; rr++) {
        const unsigned* srow = scoresU + rr * 1024;
        unsigned v[32];
#pragma unroll
        for (int j = 0; j < 32; j++)
            v[j] = (srow[lane + 32 * j] & ~31u) | (unsigned)j;   // conflict-free

#pragma unroll
        for (int it = 0; it < TOPK; it++) {
            unsigned lm = v[0];
#pragma unroll
            for (int j = 1; j < 32; j++) lm = max(lm, v[j]);
            unsigned gm = __reduce_max_sync(0xffffffffu, lm);
            unsigned ball = __ballot_sync(0xffffffffu, lm == gm);
            int wl = __ffs(ball) - 1;                    // deterministic winner
            if (lane == wl) {
                int jj = (int)(gm & 31u);
                topi[rr * 16 + it] = lane + 32 * jj;
#pragma unroll
                for (int j = 0; j < 32; j++)
                    if (j == jj) v[j] = 0u;
            }
        }
        __syncwarp();

        // exact-score closed-form sparse softmax
        float sv = 0.f;
        if (lane < TOPK)
            sv = mono_unpack(srow[topi[rr * 16 + lane]]);   // exact fp32 score
        float s0 = __shfl_sync(0xffffffffu, sv, 0);
        float Mx = fmaxf(0.f, s0);
        float c  = expf(-Mx);
        float ww = (lane < TOPK) ? expf(sv - Mx) : 0.f;
        float s = ww;
#pragma unroll
        for (int off = 16; off; off >>= 1)
            s += __shfl_xor_sync(0xffffffffu, s, off);
        float Z = s + (float)(N_ - TOPK) * c;
        if (lane < TOPK) wsh[rr * 16 + lane] = (ww - c) / Z;
        if (lane == 0)   csh[rr] = c / Z;
    }
    __syncthreads();

    // ---- epilogue: 8 threads/row, 8 d-floats each ----
    {
        int r = tid >> 3, q8 = tid & 7;
        size_t vbase = ((size_t)b * N_) * KV_C + C_ + (size_t)h * D_ + q8 * 8;
        float4 o0 = make_float4(0, 0, 0, 0), o1 = make_float4(0, 0, 0, 0);
#pragma unroll
        for (int i = 0; i < TOPK; i++) {
            int   idx = topi[r * 16 + i];
            float wv  = wsh[r * 16 + i];
            const float* vp = &g_kv[vbase + (size_t)idx * KV_C];
            float4 v0 = *(const float4*)vp;
            float4 v1 = *(const float4*)(vp + 4);
            o0.x += wv*v0.x; o0.y += wv*v0.y; o0.z += wv*v0.z; o0.w += wv*v0.w;
            o1.x += wv*v1.x; o1.y += wv*v1.y; o1.z += wv*v1.z; o1.w += wv*v1.w;
        }
        float cz = csh[r];
        float4 s0 = *(const float4*)&vs[bh * 64 + q8 * 8];
        float4 s1 = *(const float4*)&vs[bh * 64 + q8 * 8 + 4];
        o0.x += cz*s0.x; o0.y += cz*s0.y; o0.z += cz*s0.z; o0.w += cz*s0.w;
        o1.x += cz*s1.x; o1.y += cz*s1.y; o1.z += cz*s1.z; o1.w += cz*s1.w;
        float* op = &out[((size_t)(b * N_ + n0 + r)) * C_ + (size_t)h * D_ + q8 * 8];
        *(float4*)op = o0;
        *(float4*)(op + 4) = o1;
    }
}

// ---------------------------------------------------------------------------
extern "C" void kernel_launch(void* const* d_in, const int* in_sizes, int n_in,
                              void* d_out, int out_size)
{
    const float* x   = (const float*)d_in[0];
    const float* Wq  = (const float*)d_in[1];
    const float* bq  = (const float*)d_in[2];
    const float* Wkv = (const float*)d_in[3];
    const float* bkv = (const float*)d_in[4];
    const float* Wp  = (const float*)d_in[5];
    const float* bp  = (const float*)d_in[6];
    float* out = (float*)d_out;

    float *gq, *gkv, *gatt, *gvs;
    cudaGetSymbolAddress((void**)&gq,  g_q);
    cudaGetSymbolAddress((void**)&gkv, g_kv);
    cudaGetSymbolAddress((void**)&gatt, g_att);
    cudaGetSymbolAddress((void**)&gvs, g_vsum);

    // 1. Q = relu(x @ Wq + bq)
    gemm_kernel<true><<<dim3(C_ / 128, M_ / 128), 256>>>(x, Wq, bq, gq, C_, C_);
    // 2. KV = x @ Wkv + bkv
    gemm_kernel<false><<<dim3(KV_C / 128, M_ / 128), 256>>>(x, Wkv, bkv, gkv, C_, KV_C);
    // 3. vsum
    vsum_kernel<<<B_ * H_, 256>>>(gvs);
    // 4. fused scores + topk + sparse softmax + gather
    cudaFuncSetAttribute(attn_kernel, cudaFuncAttributeMaxDynamicSharedMemorySize,
                         ATTN_SMEM_BYTES);
    attn_kernel<<<dim3(N_ / ROWS, B_ * H_), 256, ATTN_SMEM_BYTES>>>(gatt, gvs);
    // 5. out = att @ Wp + bp
    gemm_kernel<false><<<dim3(C_ / 128, M_ / 128), 256>>>(gatt, Wp, bp, out, C_, C_);
}

// round 10
// speedup vs baseline: 1.5131x; 1.3299x over previous
#include <cuda_runtime.h>

#define B_   8
#define N_   1024
#define C_   512
#define H_   8
#define D_   64
#define TOPK 16
#define M_   (B_ * N_)          // 8192 rows
#define KV_C (2 * C_)           // 1024
#define NROWS ((size_t)B_ * H_ * N_)   // 65536 score rows

// Scratch (device globals; no allocation allowed)
__device__ float g_q[M_ * C_];          // relu(x@Wq+bq)
__device__ float g_kv[M_ * KV_C];       // x@Wkv+bkv  (k at [0,512), v at [512,1024))
__device__ float g_att[M_ * C_];        // attention output (pre-projection)
__device__ float g_vsum[B_ * H_ * D_];  // per-(b,h) column sums of v
__device__ unsigned g_su[NROWS * N_];   // mono-packed scores, 256MB

// ---------------------------------------------------------------------------
// Tiled fp32 GEMM: C = act(A[M,K] @ W[K,Nc] + bias). At FFMA roofline.
// ---------------------------------------------------------------------------
template <bool RELU>
__global__ __launch_bounds__(256) void gemm_kernel(
    const float* __restrict__ A, const float* __restrict__ W,
    const float* __restrict__ bias, float* __restrict__ Cc, int K, int Nc)
{
    __shared__ float As[8][132];
    __shared__ float Bs[8][128];

    int tid = threadIdx.x;
    int tx  = tid & 15;
    int ty  = tid >> 4;
    int rowTile = blockIdx.y * 128;
    int colTile = blockIdx.x * 128;

    int arow = tid >> 1;
    int aseg = (tid & 1) * 4;
    int bkr  = tid >> 5;
    int bcol = (tid & 31) * 4;

    const float* Aptr = A + (size_t)(rowTile + arow) * K + aseg;
    const float* Bptr = W + (size_t)bkr * Nc + colTile + bcol;

    float acc[8][8];
#pragma unroll
    for (int i = 0; i < 8; i++)
#pragma unroll
        for (int j = 0; j < 8; j++) acc[i][j] = 0.f;

    for (int kt = 0; kt < K; kt += 8) {
        float4 av = *(const float4*)(Aptr + kt);
        float4 bv = *(const float4*)(Bptr + (size_t)kt * Nc);
        As[aseg + 0][arow] = av.x;
        As[aseg + 1][arow] = av.y;
        As[aseg + 2][arow] = av.z;
        As[aseg + 3][arow] = av.w;
        *(float4*)&Bs[bkr][bcol] = bv;
        __syncthreads();
#pragma unroll
        for (int kk = 0; kk < 8; kk++) {
            float a[8], b[8];
            *(float4*)(a)     = *(const float4*)&As[kk][ty * 8];
            *(float4*)(a + 4) = *(const float4*)&As[kk][ty * 8 + 4];
            *(float4*)(b)     = *(const float4*)&Bs[kk][tx * 8];
            *(float4*)(b + 4) = *(const float4*)&Bs[kk][tx * 8 + 4];
#pragma unroll
            for (int i = 0; i < 8; i++)
#pragma unroll
                for (int j = 0; j < 8; j++)
                    acc[i][j] += a[i] * b[j];
        }
        __syncthreads();
    }

#pragma unroll
    for (int i = 0; i < 8; i++) {
        float* crow = Cc + (size_t)(rowTile + ty * 8 + i) * Nc + colTile + tx * 8;
#pragma unroll
        for (int j = 0; j < 8; j += 4) {
            float4 o;
            o.x = acc[i][j + 0] + bias[colTile + tx * 8 + j + 0];
            o.y = acc[i][j + 1] + bias[colTile + tx * 8 + j + 1];
            o.z = acc[i][j + 2] + bias[colTile + tx * 8 + j + 2];
            o.w = acc[i][j + 3] + bias[colTile + tx * 8 + j + 3];
            if (RELU) {
                o.x = fmaxf(o.x, 0.f); o.y = fmaxf(o.y, 0.f);
                o.z = fmaxf(o.z, 0.f); o.w = fmaxf(o.w, 0.f);
            }
            *(float4*)(crow + j) = o;
        }
    }
}

// ---------------------------------------------------------------------------
// vsum[b,h,d] = sum_n v[b,h,n,d]
// ---------------------------------------------------------------------------
__global__ __launch_bounds__(256) void vsum_kernel(float* __restrict__ vs)
{
    __shared__ float red[256];
    int bh = blockIdx.x;
    int b = bh >> 3, h = bh & 7;
    int tid = threadIdx.x;
    int d = tid & 63, chunk = tid >> 6;

    size_t base = ((size_t)b * N_) * KV_C + C_ + (size_t)h * D_ + d;
    float s = 0.f;
    int n0 = chunk * 256;
    for (int n = n0; n < n0 + 256; n++)
        s += g_kv[base + (size_t)n * KV_C];
    red[tid] = s;
    __syncthreads();
    if (chunk == 0)
        vs[bh * 64 + d] = red[d] + red[d + 64] + red[d + 128] + red[d + 192];
}

// ---------------------------------------------------------------------------
// Full-precision monotonic float<->uint mapping (bijective, order-preserving).
// ---------------------------------------------------------------------------
__device__ __forceinline__ unsigned mono_pack(float s)
{
    unsigned b = __float_as_uint(s);
    return b ^ (unsigned)(((int)b >> 31) | 0x80000000);
}
__device__ __forceinline__ float mono_unpack(unsigned u)
{
    unsigned b = (u & 0x80000000u) ? (u ^ 0x80000000u) : ~u;
    return __uint_as_float(b);
}

// ---------------------------------------------------------------------------
// scores_kernel: 64 q-rows x 1024 keys per block. Per warp 8 rows; per thread
// 8 rows x 4 cols. qT broadcast + staged k tiles. Writes mono-packed scores
// to g_su. 2 blocks/SM (smem ~50KB, <=128 regs).
// QT_PITCH must be EVEN: qT float2 reads need 8B alignment (R6 fault).
// ---------------------------------------------------------------------------
#define SROWS 64
#define QT_PITCH 66
#define KST_PITCH 132
#define SC_SMEM_BYTES ((64 * QT_PITCH + 64 * KST_PITCH) * 4)

__global__ __launch_bounds__(256, 2) void scores_kernel()
{
    extern __shared__ float sm[];
    float* qT  = sm;                    // [64][66]  qT[d][r]
    float* kst = qT + 64 * QT_PITCH;    // [64][132] kst[d][m]

    int bh = blockIdx.y;
    int b = bh >> 3, h = bh & 7;
    int n0 = blockIdx.x * SROWS;
    int tid = threadIdx.x;
    int w    = tid >> 5;                // warp 0..7 -> rows 8w..8w+7
    int lane = tid & 31;                // cols 4*lane..4*lane+3 per tile
    const float scale = 0.125f;

    // load 64 q rows transposed (coalesced LDG)
    {
        size_t qbase = ((size_t)(b * N_ + n0)) * C_ + (size_t)h * D_;
        for (int f = tid; f < SROWS * 64; f += 256) {
            int r = f >> 6, d = f & 63;
            qT[d * QT_PITCH + r] = g_q[qbase + (size_t)r * C_ + d];
        }
    }

    size_t kbase = ((size_t)b * N_) * KV_C + (size_t)h * D_;
    size_t rowbase = ((size_t)bh * N_ + n0);

    // k tile: 128 keys x 64 d -> 8 float4 per thread
    float4 pf[8];
#pragma unroll
    for (int i = 0; i < 8; i++) {
        int g = tid + 256 * i;
        int m = g & 127, d4 = (g >> 7) * 4;
        pf[i] = *(const float4*)&g_kv[kbase + (size_t)m * KV_C + d4];
    }

    for (int mt = 0; mt < N_; mt += 128) {
        __syncthreads();
#pragma unroll
        for (int i = 0; i < 8; i++) {
            int g = tid + 256 * i;
            int m = g & 127, d4 = (g >> 7) * 4;
            kst[(d4 + 0) * KST_PITCH + m] = pf[i].x;   // lanes->consecutive m: cf-free
            kst[(d4 + 1) * KST_PITCH + m] = pf[i].y;
            kst[(d4 + 2) * KST_PITCH + m] = pf[i].z;
            kst[(d4 + 3) * KST_PITCH + m] = pf[i].w;
        }
        __syncthreads();

        if (mt + 128 < N_) {
#pragma unroll
            for (int i = 0; i < 8; i++) {
                int g = tid + 256 * i;
                int m = g & 127, d4 = (g >> 7) * 4;
                pf[i] = *(const float4*)&g_kv[kbase + (size_t)(mt + 128 + m) * KV_C + d4];
            }
        }

        float acc[8][4];
#pragma unroll
        for (int r = 0; r < 8; r++)
#pragma unroll
            for (int c = 0; c < 4; c++) acc[r][c] = 0.f;

        const float* qTw = qT + 8 * w;          // even offset
#pragma unroll 4
        for (int d = 0; d < 64; d++) {
            float4 k4 = *(const float4*)&kst[d * KST_PITCH + 4 * lane];
            float2 q01 = *(const float2*)&qTw[d * QT_PITCH + 0];  // broadcast, 8B-aligned
            float2 q23 = *(const float2*)&qTw[d * QT_PITCH + 2];
            float2 q45 = *(const float2*)&qTw[d * QT_PITCH + 4];
            float2 q67 = *(const float2*)&qTw[d * QT_PITCH + 6];
            float q[8] = {q01.x, q01.y, q23.x, q23.y, q45.x, q45.y, q67.x, q67.y};
#pragma unroll
            for (int r = 0; r < 8; r++) {
                acc[r][0] += q[r] * k4.x; acc[r][1] += q[r] * k4.y;
                acc[r][2] += q[r] * k4.z; acc[r][3] += q[r] * k4.w;
            }
        }

#pragma unroll
        for (int r = 0; r < 8; r++) {
            uint4 p;
            p.x = mono_pack(acc[r][0] * scale);
            p.y = mono_pack(acc[r][1] * scale);
            p.z = mono_pack(acc[r][2] * scale);
            p.w = mono_pack(acc[r][3] * scale);
            *(uint4*)&g_su[(rowbase + 8 * w + r) * N_ + mt + 4 * lane] = p;
        }
    }
}

// ---------------------------------------------------------------------------
// topk_kernel: 1 warp per score row, 8 rows/block, no smem. uint4 score
// loads, exact uint-argmax top-16 (indices/weights in registers, shfl
// broadcast), closed-form sparse softmax, float2 gather epilogue.
// ---------------------------------------------------------------------------
__global__ __launch_bounds__(256) void topk_kernel(const float* __restrict__ vs)
{
    size_t row = (size_t)blockIdx.x * 8 + (threadIdx.x >> 5);
    int lane = threadIdx.x & 31;
    int bh = (int)(row >> 10);
    int n  = (int)(row & 1023);
    int b = bh >> 3, h = bh & 7;

    const unsigned* srow = g_su + row * N_;

    // load 1024 scores as 8 uint4/lane; slot j=(i*4+c) <-> col 4*lane+128*i+c
    unsigned v[32];
#pragma unroll
    for (int i = 0; i < 8; i++) {
        uint4 p = *(const uint4*)&srow[4 * lane + 128 * i];
        v[4 * i + 0] = (p.x & ~31u) | (unsigned)(4 * i + 0);
        v[4 * i + 1] = (p.y & ~31u) | (unsigned)(4 * i + 1);
        v[4 * i + 2] = (p.z & ~31u) | (unsigned)(4 * i + 2);
        v[4 * i + 3] = (p.w & ~31u) | (unsigned)(4 * i + 3);
    }

    int selidx = 0;
#pragma unroll
    for (int it = 0; it < TOPK; it++) {
        unsigned lm = v[0];
#pragma unroll
        for (int j = 1; j < 32; j++) lm = max(lm, v[j]);
        unsigned gm = __reduce_max_sync(0xffffffffu, lm);
        unsigned ball = __ballot_sync(0xffffffffu, lm == gm);
        int wl = __ffs(ball) - 1;
        int jj = (int)(gm & 31u);
        if (lane == it)
            selidx = 4 * wl + 128 * (jj >> 2) + (jj & 3);
        if (lane == wl) {
#pragma unroll
            for (int j = 0; j < 32; j++)
                if (j == jj) v[j] = 0u;
        }
    }

    // exact-score closed-form sparse softmax
    float sv = 0.f;
    if (lane < TOPK) sv = mono_unpack(srow[selidx]);
    float s0 = __shfl_sync(0xffffffffu, sv, 0);
    float Mx = fmaxf(0.f, s0);
    float c  = expf(-Mx);
    float ww = (lane < TOPK) ? expf(sv - Mx) : 0.f;
    float s = ww;
#pragma unroll
    for (int off = 16; off; off >>= 1)
        s += __shfl_xor_sync(0xffffffffu, s, off);
    float Z = s + (float)(N_ - TOPK) * c;
    float wfin = (ww - c) / Z;
    float cz = c / Z;

    // gather epilogue: each lane owns d = {2*lane, 2*lane+1}
    size_t vbase = ((size_t)b * N_) * KV_C + C_ + (size_t)h * D_ + 2 * lane;
    float2 o = make_float2(0.f, 0.f);
#pragma unroll
    for (int i = 0; i < TOPK; i++) {
        float wi = __shfl_sync(0xffffffffu, wfin, i);
        int   ii = __shfl_sync(0xffffffffu, selidx, i);
        float2 vv = *(const float2*)&g_kv[vbase + (size_t)ii * KV_C];
        o.x += wi * vv.x; o.y += wi * vv.y;
    }
    float2 sv2 = *(const float2*)&vs[bh * 64 + 2 * lane];
    o.x += cz * sv2.x; o.y += cz * sv2.y;
    *(float2*)&g_att[((size_t)(b * N_ + n)) * C_ + (size_t)h * D_ + 2 * lane] = o;
}

// ---------------------------------------------------------------------------
extern "C" void kernel_launch(void* const* d_in, const int* in_sizes, int n_in,
                              void* d_out, int out_size)
{
    const float* x   = (const float*)d_in[0];
    const float* Wq  = (const float*)d_in[1];
    const float* bq  = (const float*)d_in[2];
    const float* Wkv = (const float*)d_in[3];
    const float* bkv = (const float*)d_in[4];
    const float* Wp  = (const float*)d_in[5];
    const float* bp  = (const float*)d_in[6];
    float* out = (float*)d_out;

    float *gq, *gkv, *gatt, *gvs;
    cudaGetSymbolAddress((void**)&gq,  g_q);
    cudaGetSymbolAddress((void**)&gkv, g_kv);
    cudaGetSymbolAddress((void**)&gatt, g_att);
    cudaGetSymbolAddress((void**)&gvs, g_vsum);

    // 1. Q = relu(x @ Wq + bq)
    gemm_kernel<true><<<dim3(C_ / 128, M_ / 128), 256>>>(x, Wq, bq, gq, C_, C_);
    // 2. KV = x @ Wkv + bkv
    gemm_kernel<false><<<dim3(KV_C / 128, M_ / 128), 256>>>(x, Wkv, bkv, gkv, C_, KV_C);
    // 3. vsum
    vsum_kernel<<<B_ * H_, 256>>>(gvs);
    // 4. scores GEMM -> packed global buffer
    cudaFuncSetAttribute(scores_kernel, cudaFuncAttributeMaxDynamicSharedMemorySize,
                         SC_SMEM_BYTES);
    scores_kernel<<<dim3(N_ / SROWS, B_ * H_), 256, SC_SMEM_BYTES>>>();
    // 5. top-16 + sparse softmax + gather
    topk_kernel<<<(int)(NROWS / 8), 256>>>(gvs);
    // 6. out = att @ Wp + bp
    gemm_kernel<false><<<dim3(C_ / 128, M_ / 128), 256>>>(gatt, Wp, bp, out, C_, C_);
}